// round 7
// baseline (speedup 1.0000x reference)
#include <cuda_runtime.h>
#include <cuda_bf16.h>
#include <cstdint>

#define N_NODES 207
#define N_EDGES 1722
#define LDIM    64
#define BATCH   1024
#define N_SLOTS_PAD 256          // 4 passes * 16 warps * 4 slots
#define ADJ_CAP 5120             // >= 16 * sum_quads(max ng)
#define XROW    18               // bf16x2 (u32) row stride: even + bank-spreading

// ---------------- device-global CSR scratch (no allocs allowed) ------------
__device__ int g_rowptr4[N_SLOTS_PAD + 1];                   // entry start per SORTED SLOT
__device__ unsigned short g_order[N_SLOTS_PAD];              // slot -> node id (0xFFFF invalid)
__device__ __align__(16) unsigned short g_adj_node[ADJ_CAP]; // nbr*XROW (u32 index of bf16 row)
__device__ __align__(16) unsigned short g_adj_edge[ADJ_CAP]; // edge idx; N_EDGES = dummy (w=0)

// ---------------- setup kernel: deterministic quad-padded sorted CSR -------
__global__ __launch_bounds__(1024, 1)
void build_csr_kernel(const int* __restrict__ edge_i,
                      const int* __restrict__ edge_j) {
    __shared__ int s_ei[N_EDGES];
    __shared__ int s_ej[N_EDGES];
    __shared__ int s_ng[N_NODES];
    __shared__ int s_off[N_NODES + 1];          // deg count -> slot entry base
    __shared__ unsigned short s_ord[N_SLOTS_PAD];
    __shared__ int s_wcnt[32][208];
    const int tid  = threadIdx.x;
    const int warp = tid >> 5;
    const int lane = tid & 31;

    for (int i = tid; i < N_EDGES; i += 1024) {
        s_ei[i] = edge_i[i];
        s_ej[i] = edge_j[i];
    }
    for (int v = tid; v < N_NODES + 1; v += 1024) s_off[v] = 0;
    for (int i = tid; i < N_SLOTS_PAD; i += 1024) s_ord[i] = 0xFFFFu;
    for (int t = tid; t < ADJ_CAP; t += 1024) {
        g_adj_node[t] = 0;
        g_adj_edge[t] = (unsigned short)N_EDGES;    // dummy -> weight 0
    }
    for (int i = tid; i < 32 * 208; i += 1024) ((int*)s_wcnt)[i] = 0;
    __syncthreads();

    // degree count (order-independent)
    for (int idx = tid; idx < 2 * N_EDGES; idx += 1024) {
        const int e = idx >> 1;
        atomicAdd(&s_off[(idx & 1) ? s_ej[e] : s_ei[e]], 1);
    }
    __syncthreads();

    if (tid < N_NODES) s_ng[tid] = (s_off[tid] + 3) >> 2;
    __syncthreads();

    // parallel rank sort: desc by ng, tie asc id
    if (tid < N_NODES) {
        const int nv = s_ng[tid];
        int r = 0;
        for (int u = 0; u < N_NODES; ++u) {
            const int nu = s_ng[u];
            r += (nu > nv) || (nu == nv && u < tid);
        }
        s_ord[r] = (unsigned short)tid;
    }
    __syncthreads();

    // quad scan: 64 quads, 2 rounds of 32 (warp 0)
    if (warp == 0) {
        int carryG = 0;                       // in "quad-max groups"
        #pragma unroll
        for (int c = 0; c < 2; ++c) {
            const int q = c * 32 + lane;
            const int a0 = s_ord[4 * q + 0], a1 = s_ord[4 * q + 1];
            const int a2 = s_ord[4 * q + 2], a3 = s_ord[4 * q + 3];
            const int n0 = (a0 != 0xFFFF) ? s_ng[a0] : 0;
            const int n1 = (a1 != 0xFFFF) ? s_ng[a1] : 0;
            const int n2 = (a2 != 0xFFFF) ? s_ng[a2] : 0;
            const int n3 = (a3 != 0xFFFF) ? s_ng[a3] : 0;
            int m = n0 > n1 ? n0 : n1;
            m = m > n2 ? m : n2;
            m = m > n3 ? m : n3;
            int si = m;
            #pragma unroll
            for (int o = 1; o < 32; o <<= 1) {
                const int t = __shfl_up_sync(0xffffffffu, si, o);
                if (lane >= o) si += t;
            }
            const int base = (carryG + si - m) * 16;   // entries
            g_rowptr4[4 * q + 0] = base;
            g_rowptr4[4 * q + 1] = base + 4 * m;
            g_rowptr4[4 * q + 2] = base + 8 * m;
            g_rowptr4[4 * q + 3] = base + 12 * m;
            if (a0 != 0xFFFF) s_off[a0] = base;
            if (a1 != 0xFFFF) s_off[a1] = base + 4 * m;
            if (a2 != 0xFFFF) s_off[a2] = base + 8 * m;
            if (a3 != 0xFFFF) s_off[a3] = base + 12 * m;
            carryG += __shfl_sync(0xffffffffu, si, 31);
        }
        if (lane == 0) g_rowptr4[N_SLOTS_PAD] = carryG * 16;
    }
    __syncthreads();
    for (int i = tid; i < N_SLOTS_PAD; i += 1024) g_order[i] = s_ord[i];

    // single-chunk scatter: 4 sequential rounds per lane
    int myrank[4], myv[4], mynbr[4], mye[4];
    #pragma unroll
    for (int r = 0; r < 4; ++r) {
        const int idx = tid * 4 + r;
        const bool valid = idx < 2 * N_EDGES;
        int v = 207, nbr = 0, e = 0;                // 207 = shared dummy bucket
        if (valid) {
            e = idx >> 1;
            if (idx & 1) { v = s_ej[e]; nbr = s_ei[e]; }
            else         { v = s_ei[e]; nbr = s_ej[e]; }
        }
        const int prefix = s_wcnt[warp][v];
        const unsigned mask = __match_any_sync(0xffffffffu, v);
        const int rin = __popc(mask & ((1u << lane) - 1u));
        myv[r] = v; mynbr[r] = nbr; mye[r] = e;
        myrank[r] = prefix + rin;
        __syncwarp();
        if (lane == (__ffs(mask) - 1)) s_wcnt[warp][v] = prefix + __popc(mask);
        __syncwarp();
    }
    __syncthreads();

    // cross-warp scan per node: counts -> bases
    if (tid < 208) {
        int run = (tid < N_NODES) ? s_off[tid] : 0;
        #pragma unroll
        for (int w2 = 0; w2 < 32; ++w2) {
            const int t = s_wcnt[w2][tid];
            s_wcnt[w2][tid] = run;
            run += t;
        }
    }
    __syncthreads();

    #pragma unroll
    for (int r = 0; r < 4; ++r) {
        const int idx = tid * 4 + r;
        if (idx < 2 * N_EDGES) {
            const int pos = s_wcnt[warp][myv[r]] + myrank[r];
            g_adj_node[pos] = (unsigned short)(mynbr[r] * XROW);  // u32 row index
            g_adj_edge[pos] = (unsigned short)mye[r];
        }
    }
}

// ---------------- main kernel: 2 CTAs per batch (column halves) ------------
// blockIdx.x = b*2 + colhalf; CTA owns 32 of the 64 columns for all nodes.
// Warp = 4 sorted slots (quarters, equal padded ng); lane covers 4 columns
// via one uint2 (4 bf16). Inner loop in packed bf16x2. Row stride XROW=18
// u32 spreads quarter rows across banks. occ 4 (64 warps/SM).
#define S_XU_B    0
#define S_WADJ_B  14912
#define S_W_B     35392
#define S_WSL_B   42304
#define S_BIAS_B  43136
#define S_ROWP_B  43968
#define S_ORD_B   45008
#define S_ADJN_B  45520
#define SMEM_BYTES 55808

__device__ __forceinline__ __nv_bfloat162 as_bf2(unsigned v) {
    return *reinterpret_cast<__nv_bfloat162*>(&v);
}
__device__ __forceinline__ unsigned as_u32(__nv_bfloat162 v) {
    return *reinterpret_cast<unsigned*>(&v);
}

// 1 LDS.64 + 2 HFMA2 + 1 SHL + 1 FADD per entry
#define ENTRY(OFv, WPv) do {                                          \
    const uint2 u = *(const uint2*)(sx + (OFv));                      \
    const __nv_bfloat162 wb = as_bf2(WPv);                            \
    deg += __uint_as_float((WPv) << 16);                              \
    c0 = __hfma2(wb, as_bf2(u.x), c0);                                \
    c1 = __hfma2(wb, as_bf2(u.y), c1);                                \
} while (0)

__global__ __launch_bounds__(512, 4)
void diffusion_gcn_kernel(const float*  __restrict__ inputs,      // (B,2,N,L)
                          const float*  __restrict__ weight_diff, // (S,E)
                          const float*  __restrict__ bias_diff,   // (S,N)
                          const float*  __restrict__ weight_sl,   // (S,N)
                          const int*    __restrict__ ind,         // (B,)
                          float*        __restrict__ out)         // (B,N,L)
{
    extern __shared__ char smem[];
    unsigned*       s_xu    = (unsigned*)(smem + S_XU_B);     // bf16 tile (XROW stride)
    unsigned*       s_wadjh = (unsigned*)(smem + S_WADJ_B);   // packed bf16x2 (w,w)
    float*          s_w     = (float*)(smem + S_W_B);
    float*          s_wsl   = (float*)(smem + S_WSL_B);
    float*          s_bias  = (float*)(smem + S_BIAS_B);
    int*            s_rowp  = (int*)(smem + S_ROWP_B);
    unsigned short* s_ord   = (unsigned short*)(smem + S_ORD_B);
    unsigned short* s_adjn  = (unsigned short*)(smem + S_ADJN_B);

    const int b    = blockIdx.x >> 1;
    const int ch   = blockIdx.x & 1;          // column half
    const int tid  = threadIdx.x;
    const int slot = ind[b];
    const float* __restrict__ xg = inputs + (size_t)b * 2 * N_NODES * LDIM + ch * 32;

    // ---- phase A: stage smem -------------------------------------------
    {   // x half-rows -> bf16 tile: 207 rows x 8 float4 chunks
        for (int i = tid; i < N_NODES * 8; i += 512) {
            const int row = i >> 3;
            const int c   = i & 7;
            const float4 v = *(const float4*)(xg + row * LDIM + c * 4);
            __nv_bfloat162 h0 = __floats2bfloat162_rn(v.x, v.y);
            __nv_bfloat162 h1 = __floats2bfloat162_rn(v.z, v.w);
            uint2 p;
            p.x = as_u32(h0);
            p.y = as_u32(h1);
            *(uint2*)(s_xu + row * XROW + c * 2) = p;
        }
    }
    {
        const float* wrow = weight_diff + (size_t)slot * N_EDGES;
        for (int i = tid; i < 1728; i += 512)
            s_w[i] = (i < N_EDGES) ? wrow[i] : 0.0f;
    }
    for (int i = tid; i < N_NODES; i += 512) {
        s_wsl[i]  = weight_sl[(size_t)slot * N_NODES + i];
        s_bias[i] = bias_diff[(size_t)slot * N_NODES + i];
    }
    for (int i = tid; i < N_SLOTS_PAD + 1; i += 512) s_rowp[i] = g_rowptr4[i];
    for (int i = tid; i < N_SLOTS_PAD / 2; i += 512)
        ((unsigned*)s_ord)[i] = ((const unsigned*)g_order)[i];
    {   // adjacency offsets: 10240 B as 640 uint4
        const uint4* src = (const uint4*)g_adj_node;
        uint4* dst = (uint4*)s_adjn;
        for (int i = tid; i < ADJ_CAP / 8; i += 512) dst[i] = src[i];
    }
    __syncthreads();

    // ---- phase B: expand weights to adjacency order as packed bf16x2 ----
    for (int t = tid; t < ADJ_CAP; t += 512) {
        const float w = s_w[(int)g_adj_edge[t]];
        s_wadjh[t] = as_u32(__float2bfloat162_rn(w));   // replicate (w,w)
    }
    __syncthreads();

    // ---- phase C: gather --------------------------------------------------
    const int warp    = tid >> 5;        // 0..15
    const int lane    = tid & 31;
    const int quarter = lane >> 3;       // slot within quad
    const int hl      = lane & 7;        // 4-column group within slot
    const unsigned* sx = s_xu + 2 * hl;

    #pragma unroll 1
    for (int pass = 0; pass < 4; ++pass) {
        const int sl  = pass * 64 + warp * 4 + quarter;
        const int w   = s_ord[sl];
        const int beg = s_rowp[sl];
        const int ng  = (s_rowp[sl + 1] - beg) >> 2;   // uniform across quad

        // prefetch diagonal fp32 columns (L2-hot), consumed after the loop
        const float* xr = (w != 0xFFFF) ? (xg + w * LDIM + 4 * hl) : xg;
        const float4 x0 = *(const float4*)xr;

        __nv_bfloat162 c0 = as_bf2(0u), c1 = as_bf2(0u);
        float deg = 0.f;

        #pragma unroll 1
        for (int g = 0; g < ng; ++g) {
            const int t = beg + (g << 2);
            const ushort4 of = *(const ushort4*)(s_adjn + t);
            const uint4   wp = *(const uint4*)(s_wadjh + t);
            ENTRY(of.x, wp.x);
            ENTRY(of.y, wp.y);
            ENTRY(of.z, wp.z);
            ENTRY(of.w, wp.w);
        }

        if (w != 0xFFFF) {
            const unsigned r0 = as_u32(c0), r1 = as_u32(c1);
            const float sc = deg + 1.0f + s_wsl[w];
            const float bi = s_bias[w];
            float4 o;
            o.x = fmaf(sc, x0.x, bi - __uint_as_float(r0 << 16));
            o.y = fmaf(sc, x0.y, bi - __uint_as_float(r0 & 0xffff0000u));
            o.z = fmaf(sc, x0.z, bi - __uint_as_float(r1 << 16));
            o.w = fmaf(sc, x0.w, bi - __uint_as_float(r1 & 0xffff0000u));
            *(float4*)(out + ((size_t)b * N_NODES + w) * LDIM + ch * 32 + 4 * hl) = o;
        }
    }
}

// ---------------- launcher ---------------------------------------------
extern "C" void kernel_launch(void* const* d_in, const int* in_sizes, int n_in,
                              void* d_out, int out_size) {
    const float* inputs      = (const float*)d_in[0];
    const float* weight_diff = (const float*)d_in[1];
    const float* bias_diff   = (const float*)d_in[2];
    const float* weight_sl   = (const float*)d_in[3];
    const int*   ind         = (const int*)d_in[4];
    const int*   edge_i      = (const int*)d_in[5];
    const int*   edge_j      = (const int*)d_in[6];
    float*       out         = (float*)d_out;

    static bool attr_set = false;   // host-side config only, not a work guard
    if (!attr_set) {
        cudaFuncSetAttribute(diffusion_gcn_kernel,
                             cudaFuncAttributeMaxDynamicSharedMemorySize,
                             SMEM_BYTES);
        attr_set = true;
    }

    build_csr_kernel<<<1, 1024>>>(edge_i, edge_j);
    diffusion_gcn_kernel<<<2 * BATCH, 512, SMEM_BYTES>>>(
        inputs, weight_diff, bias_diff, weight_sl, ind, out);
}

// round 8
// speedup vs baseline: 1.2323x; 1.2323x over previous
#include <cuda_runtime.h>
#include <cuda_bf16.h>
#include <cstdint>

#define N_NODES 207
#define N_EDGES 1722
#define LDIM    64
#define BATCH   1024
#define N_SLOTS_PAD 256          // 4 passes * 16 warps * 4 slots
#define ADJ_CAP 5120             // >= 16 * sum_quads(max ng)

// ---------------- device-global CSR scratch (no allocs allowed) ------------
__device__ int g_rowptr4[N_SLOTS_PAD + 1];                   // entry start per SORTED SLOT
__device__ unsigned short g_order[N_SLOTS_PAD];              // slot -> node id (0xFFFF invalid)
__device__ __align__(16) unsigned short g_adj_node[ADJ_CAP]; // nbr*128 (byte offset of bf16 row)
__device__ __align__(16) unsigned short g_adj_edge[ADJ_CAP]; // edge idx; N_EDGES = dummy (w=0)

// ---------------- setup kernel: deterministic quad-padded sorted CSR -------
__global__ __launch_bounds__(1024, 1)
void build_csr_kernel(const int* __restrict__ edge_i,
                      const int* __restrict__ edge_j) {
    __shared__ int s_ei[N_EDGES];
    __shared__ int s_ej[N_EDGES];
    __shared__ int s_ng[N_NODES];
    __shared__ int s_off[N_NODES + 1];          // deg count -> slot entry base
    __shared__ unsigned short s_ord[N_SLOTS_PAD];
    __shared__ int s_wcnt[32][208];
    const int tid  = threadIdx.x;
    const int warp = tid >> 5;
    const int lane = tid & 31;

    for (int i = tid; i < N_EDGES; i += 1024) {
        s_ei[i] = edge_i[i];
        s_ej[i] = edge_j[i];
    }
    for (int v = tid; v < N_NODES + 1; v += 1024) s_off[v] = 0;
    for (int i = tid; i < N_SLOTS_PAD; i += 1024) s_ord[i] = 0xFFFFu;
    for (int t = tid; t < ADJ_CAP; t += 1024) {
        g_adj_node[t] = 0;
        g_adj_edge[t] = (unsigned short)N_EDGES;    // dummy -> weight 0
    }
    for (int i = tid; i < 32 * 208; i += 1024) ((int*)s_wcnt)[i] = 0;
    __syncthreads();

    // degree count (order-independent)
    for (int idx = tid; idx < 2 * N_EDGES; idx += 1024) {
        const int e = idx >> 1;
        atomicAdd(&s_off[(idx & 1) ? s_ej[e] : s_ei[e]], 1);
    }
    __syncthreads();

    if (tid < N_NODES) s_ng[tid] = (s_off[tid] + 3) >> 2;
    __syncthreads();

    // parallel rank sort: desc by ng, tie asc id
    if (tid < N_NODES) {
        const int nv = s_ng[tid];
        int r = 0;
        for (int u = 0; u < N_NODES; ++u) {
            const int nu = s_ng[u];
            r += (nu > nv) || (nu == nv && u < tid);
        }
        s_ord[r] = (unsigned short)tid;
    }
    __syncthreads();

    // quad scan: 64 quads, 2 rounds of 32 (warp 0)
    if (warp == 0) {
        int carryG = 0;                       // in "quad-max groups"
        #pragma unroll
        for (int c = 0; c < 2; ++c) {
            const int q = c * 32 + lane;
            const int a0 = s_ord[4 * q + 0], a1 = s_ord[4 * q + 1];
            const int a2 = s_ord[4 * q + 2], a3 = s_ord[4 * q + 3];
            const int n0 = (a0 != 0xFFFF) ? s_ng[a0] : 0;
            const int n1 = (a1 != 0xFFFF) ? s_ng[a1] : 0;
            const int n2 = (a2 != 0xFFFF) ? s_ng[a2] : 0;
            const int n3 = (a3 != 0xFFFF) ? s_ng[a3] : 0;
            int m = n0 > n1 ? n0 : n1;
            m = m > n2 ? m : n2;
            m = m > n3 ? m : n3;
            int si = m;
            #pragma unroll
            for (int o = 1; o < 32; o <<= 1) {
                const int t = __shfl_up_sync(0xffffffffu, si, o);
                if (lane >= o) si += t;
            }
            const int base = (carryG + si - m) * 16;   // entries
            g_rowptr4[4 * q + 0] = base;
            g_rowptr4[4 * q + 1] = base + 4 * m;
            g_rowptr4[4 * q + 2] = base + 8 * m;
            g_rowptr4[4 * q + 3] = base + 12 * m;
            if (a0 != 0xFFFF) s_off[a0] = base;
            if (a1 != 0xFFFF) s_off[a1] = base + 4 * m;
            if (a2 != 0xFFFF) s_off[a2] = base + 8 * m;
            if (a3 != 0xFFFF) s_off[a3] = base + 12 * m;
            carryG += __shfl_sync(0xffffffffu, si, 31);
        }
        if (lane == 0) g_rowptr4[N_SLOTS_PAD] = carryG * 16;
    }
    __syncthreads();
    for (int i = tid; i < N_SLOTS_PAD; i += 1024) g_order[i] = s_ord[i];

    // single-chunk scatter: 4 sequential rounds per lane
    int myrank[4], myv[4], mynbr[4], mye[4];
    #pragma unroll
    for (int r = 0; r < 4; ++r) {
        const int idx = tid * 4 + r;
        const bool valid = idx < 2 * N_EDGES;
        int v = 207, nbr = 0, e = 0;                // 207 = shared dummy bucket
        if (valid) {
            e = idx >> 1;
            if (idx & 1) { v = s_ej[e]; nbr = s_ei[e]; }
            else         { v = s_ei[e]; nbr = s_ej[e]; }
        }
        const int prefix = s_wcnt[warp][v];
        const unsigned mask = __match_any_sync(0xffffffffu, v);
        const int rin = __popc(mask & ((1u << lane) - 1u));
        myv[r] = v; mynbr[r] = nbr; mye[r] = e;
        myrank[r] = prefix + rin;
        __syncwarp();
        if (lane == (__ffs(mask) - 1)) s_wcnt[warp][v] = prefix + __popc(mask);
        __syncwarp();
    }
    __syncthreads();

    // cross-warp scan per node: counts -> bases
    if (tid < 208) {
        int run = (tid < N_NODES) ? s_off[tid] : 0;
        #pragma unroll
        for (int w2 = 0; w2 < 32; ++w2) {
            const int t = s_wcnt[w2][tid];
            s_wcnt[w2][tid] = run;
            run += t;
        }
    }
    __syncthreads();

    #pragma unroll
    for (int r = 0; r < 4; ++r) {
        const int idx = tid * 4 + r;
        if (idx < 2 * N_EDGES) {
            const int pos = s_wcnt[warp][myv[r]] + myrank[r];
            g_adj_node[pos] = (unsigned short)(mynbr[r] * 128);  // byte offset of row
            g_adj_edge[pos] = (unsigned short)mye[r];
        }
    }
}

// ---------------- main kernel: one CTA (512 thr) per batch, occ 4 ----------
// Warp = 4 sorted slots (quarters, equal padded ng); lane covers 8 columns
// via one uint4 (8 bf16), quarter rows phase-aligned -> conflict-free.
// META PACKED: one u32 per entry = (bf16 weight << 16) | row byte offset,
// built in phase B directly from global CSR + global weight row (L2-hot);
// no s_w / s_adjn staging at all. smem 50.2 KB -> 4 CTAs/SM.
#define S_XU_B    0
#define S_PACK_B  26496
#define S_WSL_B   46976
#define S_BIAS_B  47808
#define S_ROWP_B  48640
#define S_ORD_B   49680
#define SMEM_BYTES 50192

__device__ __forceinline__ __nv_bfloat162 as_bf2(unsigned v) {
    return *reinterpret_cast<__nv_bfloat162*>(&v);
}
__device__ __forceinline__ unsigned as_u32(__nv_bfloat162 v) {
    return *reinterpret_cast<unsigned*>(&v);
}

// 1 LDS.128 + PRMT + LOP + FADD + 4 HFMA2 per entry
#define ENTRY(PK) do {                                                \
    const uint4 u = *(const uint4*)(sxb + ((PK) & 0xffffu));          \
    const unsigned wbu = __byte_perm((PK), (PK), 0x3232);             \
    const __nv_bfloat162 wb = as_bf2(wbu);                            \
    deg += __uint_as_float((PK) & 0xffff0000u);                       \
    c0 = __hfma2(wb, as_bf2(u.x), c0);                                \
    c1 = __hfma2(wb, as_bf2(u.y), c1);                                \
    c2 = __hfma2(wb, as_bf2(u.z), c2);                                \
    c3 = __hfma2(wb, as_bf2(u.w), c3);                                \
} while (0)

__global__ __launch_bounds__(512, 4)
void diffusion_gcn_kernel(const float*  __restrict__ inputs,      // (B,2,N,L)
                          const float*  __restrict__ weight_diff, // (S,E)
                          const float*  __restrict__ bias_diff,   // (S,N)
                          const float*  __restrict__ weight_sl,   // (S,N)
                          const int*    __restrict__ ind,         // (B,)
                          float*        __restrict__ out)         // (B,N,L)
{
    extern __shared__ char smem[];
    unsigned*       s_xu   = (unsigned*)(smem + S_XU_B);     // bf16 tile, 32 u32/row
    unsigned*       s_pack = (unsigned*)(smem + S_PACK_B);   // packed meta per entry
    float*          s_wsl  = (float*)(smem + S_WSL_B);
    float*          s_bias = (float*)(smem + S_BIAS_B);
    int*            s_rowp = (int*)(smem + S_ROWP_B);
    unsigned short* s_ord  = (unsigned short*)(smem + S_ORD_B);

    const int b    = blockIdx.x;
    const int tid  = threadIdx.x;
    const int slot = ind[b];
    const float* __restrict__ xg   = inputs + (size_t)b * 2 * N_NODES * LDIM;
    const float* __restrict__ wrow = weight_diff + (size_t)slot * N_EDGES;

    // ---- phase A: stage x tile + per-node params + meta tables ----------
    {   // x -> bf16 tile: 3312 float4 -> uint2
        const float4* src = (const float4*)xg;
        uint2* dst = (uint2*)s_xu;
        #pragma unroll 4
        for (int i = tid; i < (N_NODES * LDIM) / 4; i += 512) {
            const float4 v = src[i];
            uint2 p;
            p.x = as_u32(__floats2bfloat162_rn(v.x, v.y));
            p.y = as_u32(__floats2bfloat162_rn(v.z, v.w));
            dst[i] = p;
        }
    }
    for (int i = tid; i < N_NODES; i += 512) {
        s_wsl[i]  = weight_sl[(size_t)slot * N_NODES + i];
        s_bias[i] = bias_diff[(size_t)slot * N_NODES + i];
    }
    for (int i = tid; i < N_SLOTS_PAD + 1; i += 512) s_rowp[i] = g_rowptr4[i];
    for (int i = tid; i < N_SLOTS_PAD / 2; i += 512)
        ((unsigned*)s_ord)[i] = ((const unsigned*)g_order)[i];

    // phase B (no dependence on s_xu): packed meta from global CSR + weights
    for (int t = tid; t < ADJ_CAP; t += 512) {
        const int e = (int)g_adj_edge[t];                 // L2-hot, shared
        const float w = (e < N_EDGES) ? wrow[e] : 0.0f;
        const unsigned wb = (unsigned)__bfloat16_as_ushort(__float2bfloat16(w));
        s_pack[t] = (wb << 16) | (unsigned)g_adj_node[t]; // hi: bf16 w, lo: byte off
    }
    __syncthreads();

    // ---- phase C: gather --------------------------------------------------
    const int warp    = tid >> 5;        // 0..15
    const int lane    = tid & 31;
    const int quarter = lane >> 3;       // slot within quad
    const int hl      = lane & 7;        // 8-column group within slot
    const char* sxb   = (const char*)s_xu + 16 * hl;

    #pragma unroll 1
    for (int pass = 0; pass < 4; ++pass) {
        const int sl  = pass * 64 + warp * 4 + quarter;
        const int w   = s_ord[sl];
        const int beg = s_rowp[sl];
        const int ng  = (s_rowp[sl + 1] - beg) >> 2;   // uniform across quad

        // prefetch diagonal fp32 row chunk (global, L2-hot)
        const float* xr = (w != 0xFFFF) ? (xg + w * LDIM + 8 * hl) : xg;
        const float4 x0 = *(const float4*)xr;

        __nv_bfloat162 c0 = as_bf2(0u), c1 = as_bf2(0u);
        __nv_bfloat162 c2 = as_bf2(0u), c3 = as_bf2(0u);
        float deg = 0.f;

        #pragma unroll 1
        for (int g = 0; g < ng; ++g) {
            const uint4 p = *(const uint4*)(s_pack + beg + (g << 2));
            ENTRY(p.x);
            ENTRY(p.y);
            ENTRY(p.z);
            ENTRY(p.w);
        }

        if (w != 0xFFFF) {
            const float4 x1 = *(const float4*)(xr + 4);
            const unsigned r0 = as_u32(c0), r1 = as_u32(c1);
            const unsigned r2 = as_u32(c2), r3 = as_u32(c3);
            const float sc = deg + 1.0f + s_wsl[w];
            const float bi = s_bias[w];
            float4 o0, o1;
            o0.x = fmaf(sc, x0.x, bi - __uint_as_float(r0 << 16));
            o0.y = fmaf(sc, x0.y, bi - __uint_as_float(r0 & 0xffff0000u));
            o0.z = fmaf(sc, x0.z, bi - __uint_as_float(r1 << 16));
            o0.w = fmaf(sc, x0.w, bi - __uint_as_float(r1 & 0xffff0000u));
            o1.x = fmaf(sc, x1.x, bi - __uint_as_float(r2 << 16));
            o1.y = fmaf(sc, x1.y, bi - __uint_as_float(r2 & 0xffff0000u));
            o1.z = fmaf(sc, x1.z, bi - __uint_as_float(r3 << 16));
            o1.w = fmaf(sc, x1.w, bi - __uint_as_float(r3 & 0xffff0000u));
            float* op = out + ((size_t)b * N_NODES + w) * LDIM + 8 * hl;
            *(float4*)op = o0;
            *(float4*)(op + 4) = o1;
        }
    }
}

// ---------------- launcher ---------------------------------------------
extern "C" void kernel_launch(void* const* d_in, const int* in_sizes, int n_in,
                              void* d_out, int out_size) {
    const float* inputs      = (const float*)d_in[0];
    const float* weight_diff = (const float*)d_in[1];
    const float* bias_diff   = (const float*)d_in[2];
    const float* weight_sl   = (const float*)d_in[3];
    const int*   ind         = (const int*)d_in[4];
    const int*   edge_i      = (const int*)d_in[5];
    const int*   edge_j      = (const int*)d_in[6];
    float*       out         = (float*)d_out;

    static bool attr_set = false;   // host-side config only, not a work guard
    if (!attr_set) {
        cudaFuncSetAttribute(diffusion_gcn_kernel,
                             cudaFuncAttributeMaxDynamicSharedMemorySize,
                             SMEM_BYTES);
        attr_set = true;
    }

    build_csr_kernel<<<1, 1024>>>(edge_i, edge_j);
    diffusion_gcn_kernel<<<BATCH, 512, SMEM_BYTES>>>(
        inputs, weight_diff, bias_diff, weight_sl, ind, out);
}